// round 13
// baseline (speedup 1.0000x reference)
#include <cuda_runtime.h>

// ---- Problem constants -----------------------------------------------------
#define CC   128
#define HH   112
#define WW   112
#define HO   56
#define WO   56

// ---- Accurate logf (njuffa, max err 0.85089 ulp), fast-math-proof ----------
__device__ __forceinline__ float log_acc(float a) {
    int   e = (__float_as_int(a) - 0x3f2aaaab) & 0xff800000;
    float m = __int_as_float(__float_as_int(a) - e);
    float i = (float)e * 1.19209290e-7f;     // 2^-23
    m = m - 1.0f;
    float s = m * m;
    float r = -0.130310059f;
    float t =  0.140869141f;
    r = fmaf(r, s, -0.121483512f);
    t = fmaf(t, s,  0.139814854f);
    r = fmaf(r, s, -0.166846126f);
    t = fmaf(t, s,  0.200120345f);
    r = fmaf(r, s, -0.249996200f);
    r = fmaf(t, m, r);
    r = fmaf(r, m,  0.333331972f);
    r = fmaf(r, m, -0.500000000f);
    r = fmaf(r, s, m);
    r = fmaf(i, 0.693147182f, r);
    return r;
}

// bits -> uniform (JAX semantics) -> standard gumbel.
// NOTE: f + 1e-20 >= 1e-20 always holds bit-exactly for f in {0} U [2^-23, 1),
// so the reference's max(..., 1e-20) clamp is a no-op we can drop.
__device__ __forceinline__ float gumbel_from_bits(unsigned bits) {
    float f = __uint_as_float((bits >> 9) | 0x3f800000u) - 1.0f;  // [0,1)
    float u = f + 1e-20f;
    return -log_acc(-log_acc(u));
}

// ---- Threefry-2x32, key (0,42), partitionable mode -------------------------
// Hybrid rounds: _S uses SHF (alu pipe); _W uses IMAD.WIDE rotate (fma pipe)
// with runtime-opaque multipliers so ptxas can't strength-reduce to shifts.
// (lo | hi) ^ x0 fuses into a single LOP3.
#define TF_RND_S(r) { x0 += x1; x1 = __funnelshift_l(x1, x1, (r)) ^ x0; }
#define TF_RND_W(Kr) { x0 += x1;                                        \
    unsigned long long _m = (unsigned long long)x1 * (Kr);              \
    x1 = ((unsigned)_m | (unsigned)(_m >> 32)) ^ x0; }

__global__ __launch_bounds__(224)
void tdgs_pool_kernel(const float* __restrict__ x,
                      const float* __restrict__ temperature,
                      float* __restrict__ out) {
    // Runtime-opaque power-of-two multipliers (threadIdx.z == 0 at runtime,
    // but ptxas cannot fold it): keeps the _W rotates on the fma pipe.
    const unsigned one = 1u << threadIdx.z;
    const unsigned K15 = one << 15, K6  = one << 6;
    const unsigned K29 = one << 29, K24 = one << 24;

    const unsigned wo = threadIdx.x;                       // 0..55
    const unsigned ho = blockIdx.x * 4u + threadIdx.y;     // 0..55
    const unsigned c  = blockIdx.y;                        // 0..127
    const unsigned b  = blockIdx.z;                        // 0..31

    float tp = temperature[(c * HO + ho) * WO + wo];
    tp = fmaxf(tp, 0.0f) + 0.1f;

    const unsigned base = ((b * CC + c) * HH + 2u * ho) * WW + 2u * wo;
    const float2 a0 = *reinterpret_cast<const float2*>(x + base);
    const float2 a1 = *reinterpret_cast<const float2*>(x + base + WW);
    const float xs[4] = {a0.x, a0.y, a1.x, a1.y};

    const unsigned p   = ((b * CC + c) * HO + ho) * WO + wo;
    const unsigned ctr = 4u * p;

    float best = -__int_as_float(0x7f800000);  // -inf
    float sel  = 0.0f;

    #pragma unroll
    for (int j = 0; j < 4; j++) {
        const unsigned ks0 = 0u, ks1 = 42u, ks2 = 0x1BD11BDAu ^ 42u;
        unsigned x0 = ks0;                 // counter hi word = 0 (N < 2^32)
        unsigned x1 = (ctr + (unsigned)j) + ks1;
        TF_RND_S(13) TF_RND_W(K15) TF_RND_S(26) TF_RND_W(K6)
        x0 += ks1; x1 += ks2 + 1u;
        TF_RND_S(17) TF_RND_W(K29) TF_RND_S(16) TF_RND_W(K24)
        x0 += ks2; x1 += ks0 + 2u;
        TF_RND_S(13) TF_RND_W(K15) TF_RND_S(26) TF_RND_W(K6)
        x0 += ks0; x1 += ks1 + 3u;
        TF_RND_S(17) TF_RND_W(K29) TF_RND_S(16) TF_RND_W(K24)
        x0 += ks1; x1 += ks2 + 4u;
        TF_RND_S(13) TF_RND_W(K15) TF_RND_S(26) TF_RND_W(K6)
        x0 += ks2; x1 += ks0 + 5u;
        const unsigned bits = x0 ^ x1;     // partitionable xor-fold

        const float g = gumbel_from_bits(bits);
        const float v = __fdiv_rn(xs[j], tp) + g;
        if (v > best) { best = v; sel = xs[j]; }  // first-max wins ties
    }

    out[p] = sel;
}

extern "C" void kernel_launch(void* const* d_in, const int* in_sizes, int n_in,
                              void* d_out, int out_size) {
    const float* x    = (const float*)d_in[0];  // (32,128,112,112) f32
    const float* temp = (const float*)d_in[1];  // (128,56,56) f32
    float* out        = (float*)d_out;          // (32,128,56,56) f32
    (void)in_sizes; (void)n_in; (void)out_size;

    dim3 block(56, 4, 1);    // 224 threads
    dim3 grid(14, 128, 32);  // 14*4 = 56 = HO rows; c; b
    tdgs_pool_kernel<<<grid, block>>>(x, temp, out);
}